// round 6
// baseline (speedup 1.0000x reference)
#include <cuda_runtime.h>
#include <cuda_bf16.h>
#include <math.h>

// Problem constants
#define B_   16
#define C_   64
#define H_   160
#define W_   160
#define PD   32
#define HW   (H_*W_)
#define LK_  13
#define PADK 6
#define TX   16
#define TYR  32
#define ITH  (TYR + 2*PADK)   // 44
#define ITW  (TX  + 2*PADK)   // 28
#define IN_CH    (ITH*ITW)        // 1232
#define IN_ELEMS (PD*IN_CH)       // 39424
#define FSTRIDE 32                // [tap][co] stride
#define FSLICE  (169*FSTRIDE)     // 5408 floats per slice
#define NFB 3                     // filter buffers (distance-2 staging)
#define NTHR 512

typedef unsigned long long ull;

__device__ float g_gap[B_ * PD];
__device__ float g_dk[B_ * PD * 9];

// ---------------- packed f32x2 helpers ----------------
__device__ __forceinline__ ull dup2(float a) {
    ull r;
    asm("mov.b64 %0, {%1, %1};" : "=l"(r) : "f"(a));
    return r;
}
__device__ __forceinline__ void fma2(ull& d, ull a, ull b) {
    asm("fma.rn.f32x2 %0, %1, %2, %0;" : "+l"(d) : "l"(a), "l"(b));
}
__device__ __forceinline__ float2 unpk(ull v) {
    float2 f;
    asm("mov.b64 {%0, %1}, %2;" : "=f"(f.x), "=f"(f.y) : "l"(v));
    return f;
}
__device__ __forceinline__ void cp4(float* dst, const float* src) {
    unsigned d = (unsigned)__cvta_generic_to_shared(dst);
    asm volatile("cp.async.ca.shared.global [%0], [%1], 4;" :: "r"(d), "l"(src));
}
__device__ __forceinline__ void cp4z(float* dst, const float* src, bool ok, const float* safe) {
    unsigned d = (unsigned)__cvta_generic_to_shared(dst);
    int sz = ok ? 4 : 0;
    const float* s = ok ? src : safe;
    asm volatile("cp.async.ca.shared.global [%0], [%1], 4, %2;" :: "r"(d), "l"(s), "r"(sz));
}

// ---------------- kernel 1: GAP over H,W for first 32 ch ----------------
__global__ void gap_kernel(const float* __restrict__ x) {
    int bc = blockIdx.x;
    int b  = bc >> 5;
    int c  = bc & 31;
    const float4* p = (const float4*)(x + (size_t)(b * C_ + c) * HW);
    float s = 0.f;
    for (int i = threadIdx.x; i < HW / 4; i += 256) {
        float4 v = p[i];
        s += (v.x + v.y) + (v.z + v.w);
    }
    __shared__ float red[256];
    red[threadIdx.x] = s;
    __syncthreads();
    for (int st = 128; st > 0; st >>= 1) {
        if (threadIdx.x < st) red[threadIdx.x] += red[threadIdx.x + st];
        __syncthreads();
    }
    if (threadIdx.x == 0) g_gap[bc] = red[0] * (1.0f / (float)HW);
}

// ---------------- kernel 2: tiny MLP -> dk[b][c][3][3] ----------------
__global__ void mlp_kernel(const float* __restrict__ w1, const float* __restrict__ b1,
                           const float* __restrict__ w2, const float* __restrict__ b2) {
    __shared__ float h[B_ * 16];
    int t = threadIdx.x;           // 288 threads
    if (t < 256) {
        int b = t >> 4, j = t & 15;
        float s = b1[j];
#pragma unroll
        for (int c = 0; c < 32; c++) s += g_gap[b * 32 + c] * w1[j * 32 + c];
        h[t] = 0.5f * s * (1.0f + erff(s * 0.7071067811865476f));
    }
    __syncthreads();
    for (int idx = t; idx < B_ * 288; idx += 288) {
        int b = idx / 288, k = idx % 288;
        float s = b2[k];
#pragma unroll
        for (int j = 0; j < 16; j++) s += h[b * 16 + j] * w2[k * 16 + j];
        g_dk[idx] = s;
    }
}

// ---------------- main kernel ----------------
// 13x13 conv (32->32), dynamic 3x3 folded into filter slice diagonal.
// block 512 thr: tx=tid&15, tz=(tid>>4)&1 (co half), ty=tid>>5 (0..15).
// per thread: 2 px (rows ty, ty+16) x 16 co = 16 f32x2 accs.
// grid (10,5,16) = 800. 1 CTA/SM, 16 warps = 4/SMSP. smem 223.7 KB.
__global__ __launch_bounds__(NTHR, 1)
void conv_main(const float* __restrict__ x, const float* __restrict__ flt,
               float* __restrict__ out) {
    extern __shared__ float sm[];
    float* sIn  = sm;                         // 39424
    float* sFlt = sm + IN_ELEMS;              // 3 * 5408
    float* sDk  = sFlt + NFB * FSLICE;        // 288

    const int b   = blockIdx.z;
    const int x0  = blockIdx.x * TX;
    const int y0  = blockIdx.y * TYR;
    const int tid = threadIdx.x;
    const int tx  = tid & 15;
    const int tz  = (tid >> 4) & 1;
    const int ty  = tid >> 5;
    const int coB = tz * 16;

    const float* xb = x + (size_t)b * C_ * HW;

    for (int i = tid; i < PD * 9; i += NTHR) sDk[i] = g_dk[b * PD * 9 + i];

    // filter slice ci -> buffer bi, layout [tap][co]
    #define STAGE_FILTER(ci, bi) do {                                         \
        float* fdst = sFlt + (bi) * FSLICE;                                   \
        int co = tid >> 4, t0 = tid & 15;                                     \
        const float* src = flt + ((size_t)co * PD + (ci)) * 169;              \
        for (int t = t0; t < 169; t += 16) cp4(fdst + t * FSTRIDE + co, src + t); \
    } while (0)

    // prologue: G0 = {full input tile, filter0->buf0}, G1 = {filter1->buf1}
    for (int i = tid; i < IN_ELEMS; i += NTHR) {
        int ci  = i / IN_CH;
        int rem = i - ci * IN_CH;
        int r = rem / ITW, c = rem - r * ITW;
        int gy = y0 - PADK + r, gx = x0 - PADK + c;
        bool ok = ((unsigned)gy < (unsigned)H_) & ((unsigned)gx < (unsigned)W_);
        cp4z(sIn + i, xb + ci * HW + gy * W_ + gx, ok, xb);
    }
    STAGE_FILTER(0, 0);
    asm volatile("cp.async.commit_group;" ::: "memory");
    STAGE_FILTER(1, 1);
    asm volatile("cp.async.commit_group;" ::: "memory");

    ull acc[2][8];
#pragma unroll
    for (int p = 0; p < 2; p++)
#pragma unroll
        for (int q = 0; q < 8; q++) acc[p][q] = 0ULL;

    int fbi = 0;                 // ci % 3
    int sbi = 2;                 // (ci+2) % 3
    for (int ci = 0; ci < PD; ci++) {
        asm volatile("cp.async.wait_group 1;" ::: "memory");
        __syncthreads();                         // slice ci (+input on first iter) visible

        float* fb = sFlt + fbi * FSLICE;
        // fold dynamic 3x3 into diagonal (co==ci) of this slice
        if (tid < 9) {
            int i = tid / 3, j = tid - 3 * i;
            fb[((i + 5) * LK_ + (j + 5)) * FSTRIDE + ci] += sDk[ci * 9 + tid];
        }
        int nc = ci + 2;
        if (nc < PD) STAGE_FILTER(nc, sbi);
        asm volatile("cp.async.commit_group;" ::: "memory");  // possibly empty group
        __syncthreads();                         // fold visible

        const float* inC = sIn + ci * IN_CH;
#pragma unroll 1
        for (int ky = 0; ky < LK_; ky++) {
            const float* rA   = inC + (ty + ky) * ITW + tx;
            const float* rB   = rA + 16 * ITW;
            const float* wrow = fb + (ky * LK_) * FSTRIDE + coB;
#pragma unroll
            for (int kx = 0; kx < LK_; kx++) {
                const float* wp = wrow + kx * FSTRIDE;
                ulonglong2 pA = *(const ulonglong2*)(wp);        // co 0..3
                ulonglong2 pB = *(const ulonglong2*)(wp + 4);    // co 4..7
                ulonglong2 pC = *(const ulonglong2*)(wp + 8);    // co 8..11
                ulonglong2 pD = *(const ulonglong2*)(wp + 12);   // co 12..15
                ull dA = dup2(rA[kx]);
                ull dB = dup2(rB[kx]);
                fma2(acc[0][0], dA, pA.x); fma2(acc[0][1], dA, pA.y);
                fma2(acc[0][2], dA, pB.x); fma2(acc[0][3], dA, pB.y);
                fma2(acc[0][4], dA, pC.x); fma2(acc[0][5], dA, pC.y);
                fma2(acc[0][6], dA, pD.x); fma2(acc[0][7], dA, pD.y);
                fma2(acc[1][0], dB, pA.x); fma2(acc[1][1], dB, pA.y);
                fma2(acc[1][2], dB, pB.x); fma2(acc[1][3], dB, pB.y);
                fma2(acc[1][4], dB, pC.x); fma2(acc[1][5], dB, pC.y);
                fma2(acc[1][6], dB, pD.x); fma2(acc[1][7], dB, pD.y);
            }
        }
        fbi = (fbi == 2) ? 0 : fbi + 1;
        sbi = (sbi == 2) ? 0 : sbi + 1;
    }

    // ---- epilogue: store (dyn conv folded into filter) ----
#pragma unroll
    for (int p = 0; p < 2; p++) {
        int gy = y0 + ty + p * 16;
#pragma unroll
        for (int q = 0; q < 8; q++) {
            float2 v = unpk(acc[p][q]);
            int c = coB + 2 * q;
            size_t off = (((size_t)b * C_ + c) * H_ + gy) * W_ + x0 + tx;
            out[off]      = v.x;
            out[off + HW] = v.y;
        }
    }

    // ---- fused x2 passthrough copy (channels 32..63, this tile) ----
    for (int idx = tid; idx < PD * TYR * (TX / 4); idx += NTHR) {   // 4096 float4
        int ch2 = idx >> 7;
        int rem = idx & 127;
        int row = rem >> 2, c4 = rem & 3;
        size_t off = (((size_t)b * C_ + PD + ch2) * H_ + y0 + row) * W_ + x0 + c4 * 4;
        *(float4*)(out + off) = *(const float4*)(x + off);
    }
    #undef STAGE_FILTER
}

// ---------------- launch ----------------
extern "C" void kernel_launch(void* const* d_in, const int* in_sizes, int n_in,
                              void* d_out, int out_size) {
    const float* x  = (const float*)d_in[0];
    const float* lk = (const float*)d_in[1];
    const float* w1 = (const float*)d_in[2];
    const float* b1 = (const float*)d_in[3];
    const float* w2 = (const float*)d_in[4];
    const float* b2 = (const float*)d_in[5];
    float* out = (float*)d_out;

    const int smem_bytes = (IN_ELEMS + NFB * FSLICE + PD * 9) * (int)sizeof(float); // 223744
    cudaFuncSetAttribute(conv_main, cudaFuncAttributeMaxDynamicSharedMemorySize, smem_bytes);

    gap_kernel<<<B_ * PD, 256>>>(x);
    mlp_kernel<<<1, 288>>>(w1, b1, w2, b2);

    dim3 grid(W_ / TX, H_ / TYR, B_);
    conv_main<<<grid, NTHR, smem_bytes>>>(x, lk, out);
}

// round 7
// speedup vs baseline: 1.2676x; 1.2676x over previous
#include <cuda_runtime.h>
#include <cuda_bf16.h>
#include <math.h>

// Problem constants
#define B_   16
#define C_   64
#define H_   160
#define W_   160
#define PD   32
#define HW   (H_*W_)
#define LK_  13
#define PADK 6
#define TX   16          // tile width
#define TYR  32          // tile height
#define ITH  (TYR + 2*PADK)  // 44
#define ITW  (TX  + 2*PADK)  // 28
#define FSTRIDE 36           // filter [tap][co] stride (16B aligned at co 0/16)
#define FSLICE  (169*FSTRIDE)  // 6084 floats per ci slice
#define IN_ELEMS (PD*ITH*ITW)  // 39424

typedef unsigned long long ull;

__device__ float g_gap[B_ * PD];
__device__ float g_dk[B_ * PD * 9];

// ---------------- packed f32x2 helpers ----------------
__device__ __forceinline__ ull dup2(float a) {
    ull r;
    asm("mov.b64 %0, {%1, %1};" : "=l"(r) : "f"(a));
    return r;
}
__device__ __forceinline__ void fma2(ull& d, ull a, ull b) {
    asm("fma.rn.f32x2 %0, %1, %2, %0;" : "+l"(d) : "l"(a), "l"(b));
}
__device__ __forceinline__ float2 unpk(ull v) {
    float2 f;
    asm("mov.b64 {%0, %1}, %2;" : "=f"(f.x), "=f"(f.y) : "l"(v));
    return f;
}
__device__ __forceinline__ void cp4(float* dst, const float* src) {
    unsigned d = (unsigned)__cvta_generic_to_shared(dst);
    asm volatile("cp.async.ca.shared.global [%0], [%1], 4;" :: "r"(d), "l"(src));
}

// ---------------- kernel 1: GAP over H,W for first 32 ch ----------------
__global__ void gap_kernel(const float* __restrict__ x) {
    int bc = blockIdx.x;
    int b  = bc >> 5;
    int c  = bc & 31;
    const float4* p = (const float4*)(x + (size_t)(b * C_ + c) * HW);
    float s = 0.f;
    for (int i = threadIdx.x; i < HW / 4; i += 256) {
        float4 v = p[i];
        s += (v.x + v.y) + (v.z + v.w);
    }
    __shared__ float red[256];
    red[threadIdx.x] = s;
    __syncthreads();
    for (int st = 128; st > 0; st >>= 1) {
        if (threadIdx.x < st) red[threadIdx.x] += red[threadIdx.x + st];
        __syncthreads();
    }
    if (threadIdx.x == 0) g_gap[bc] = red[0] * (1.0f / (float)HW);
}

// ---------------- kernel 2: tiny MLP -> dk[b][c][3][3] ----------------
__global__ void mlp_kernel(const float* __restrict__ w1, const float* __restrict__ b1,
                           const float* __restrict__ w2, const float* __restrict__ b2) {
    __shared__ float h[B_ * 16];
    int t = threadIdx.x;           // 288 threads
    if (t < 256) {
        int b = t >> 4, j = t & 15;
        float s = b1[j];
#pragma unroll
        for (int c = 0; c < 32; c++) s += g_gap[b * 32 + c] * w1[j * 32 + c];
        h[t] = 0.5f * s * (1.0f + erff(s * 0.7071067811865476f));
    }
    __syncthreads();
    for (int idx = t; idx < B_ * 288; idx += 288) {
        int b = idx / 288, k = idx % 288;
        float s = b2[k];
#pragma unroll
        for (int j = 0; j < 16; j++) s += h[b * 16 + j] * w2[k * 16 + j];
        g_dk[idx] = s;
    }
}

// ---------------- profiling-alignment no-op ----------------
__global__ void nop_kernel() {}

// ---------------- main: 13x13 conv (32->32) + fused dyn 3x3 dw + x2 copy ----------------
// block: 256 threads; tx = tid&15, ty = (tid>>4)&7, tz = tid>>7 (warp-uniform tz)
// each thread: 4 y-pixels x 16 co (32 f32x2 accumulators); software-pipelined taps.
// grid: (10, 5, 16)
__global__ __launch_bounds__(256, 1)
void conv_main(const float* __restrict__ x, const float* __restrict__ flt,
               float* __restrict__ out) {
    extern __shared__ float sm[];
    float* sIn  = sm;                         // 39424 floats
    float* sFlt = sm + IN_ELEMS;              // 2 * 6084 floats (double buffered)
    float* sDk  = sFlt + 2 * FSLICE;          // 288 floats

    const int b   = blockIdx.z;
    const int x0  = blockIdx.x * TX;
    const int y0  = blockIdx.y * TYR;
    const int tid = threadIdx.x;
    const int tx  = tid & 15;
    const int ty  = (tid >> 4) & 7;
    const int tz  = tid >> 7;
    const int coB = tz * 16;
    const int ty4 = ty * 4;

    // ---- load input tile (32 ci, halo 6, zero padded) ----
    const float* xb = x + (size_t)b * C_ * HW;
    for (int i = tid; i < IN_ELEMS; i += 256) {
        int ci  = i / (ITH * ITW);
        int rem = i - ci * (ITH * ITW);
        int r = rem / ITW, c = rem - r * ITW;
        int gy = y0 - PADK + r, gx = x0 - PADK + c;
        float v = 0.f;
        if ((unsigned)gy < (unsigned)H_ && (unsigned)gx < (unsigned)W_)
            v = xb[ci * HW + gy * W_ + gx];
        sIn[i] = v;
    }
    for (int i = tid; i < PD * 9; i += 256) sDk[i] = g_dk[b * PD * 9 + i];

    // ---- stage filter slice ci=0 via cp.async (transposed to [tap][co]) ----
    {
        int co = tid >> 3, t0 = tid & 7;
        const float* src = flt + ((size_t)co * PD + 0) * 169;
        for (int t = t0; t < 169; t += 8) cp4(sFlt + t * FSTRIDE + co, src + t);
        asm volatile("cp.async.commit_group;" ::: "memory");
    }

    ull acc[4][8];
#pragma unroll
    for (int p = 0; p < 4; p++)
#pragma unroll
        for (int q = 0; q < 8; q++) acc[p][q] = 0ULL;

    for (int ci = 0; ci < PD; ci++) {
        asm volatile("cp.async.wait_group 0;" ::: "memory");
        __syncthreads();   // staged slice visible; prior compute done before overwrite
        if (ci + 1 < PD) {
            int co = tid >> 3, t0 = tid & 7;
            const float* src = flt + ((size_t)co * PD + ci + 1) * 169;
            float* dst = sFlt + ((ci + 1) & 1) * FSLICE;
            for (int t = t0; t < 169; t += 8) cp4(dst + t * FSTRIDE + co, src + t);
            asm volatile("cp.async.commit_group;" ::: "memory");
        }

        const float* fb  = sFlt + (ci & 1) * FSLICE;
        const float* inC = sIn + ci * (ITH * ITW);
#pragma unroll 1
        for (int ky = 0; ky < LK_; ky++) {
            const float* rbase = inC + (ty4 + ky) * ITW + tx;
            const float* wrow  = fb + (ky * LK_) * FSTRIDE + coB;

            // preload tap kx=0 (weights + inputs)
            ulonglong2 cA = *(const ulonglong2*)(wrow);
            ulonglong2 cB = *(const ulonglong2*)(wrow + 4);
            ulonglong2 cC = *(const ulonglong2*)(wrow + 8);
            ulonglong2 cD = *(const ulonglong2*)(wrow + 12);
            ull e0 = dup2(rbase[0]);
            ull e1 = dup2(rbase[ITW]);
            ull e2 = dup2(rbase[2 * ITW]);
            ull e3 = dup2(rbase[3 * ITW]);

#pragma unroll
            for (int kx = 0; kx < LK_; kx++) {
                ulonglong2 nA, nB, nC, nD;
                ull f0, f1, f2, f3;
                if (kx < LK_ - 1) {   // prefetch tap kx+1 before current FMAs
                    const float* wp = wrow + (kx + 1) * FSTRIDE;
                    nA = *(const ulonglong2*)(wp);
                    nB = *(const ulonglong2*)(wp + 4);
                    nC = *(const ulonglong2*)(wp + 8);
                    nD = *(const ulonglong2*)(wp + 12);
                    f0 = dup2(rbase[kx + 1]);
                    f1 = dup2(rbase[kx + 1 + ITW]);
                    f2 = dup2(rbase[kx + 1 + 2 * ITW]);
                    f3 = dup2(rbase[kx + 1 + 3 * ITW]);
                }
                fma2(acc[0][0], e0, cA.x); fma2(acc[0][1], e0, cA.y);
                fma2(acc[0][2], e0, cB.x); fma2(acc[0][3], e0, cB.y);
                fma2(acc[0][4], e0, cC.x); fma2(acc[0][5], e0, cC.y);
                fma2(acc[0][6], e0, cD.x); fma2(acc[0][7], e0, cD.y);
                fma2(acc[1][0], e1, cA.x); fma2(acc[1][1], e1, cA.y);
                fma2(acc[1][2], e1, cB.x); fma2(acc[1][3], e1, cB.y);
                fma2(acc[1][4], e1, cC.x); fma2(acc[1][5], e1, cC.y);
                fma2(acc[1][6], e1, cD.x); fma2(acc[1][7], e1, cD.y);
                fma2(acc[2][0], e2, cA.x); fma2(acc[2][1], e2, cA.y);
                fma2(acc[2][2], e2, cB.x); fma2(acc[2][3], e2, cB.y);
                fma2(acc[2][4], e2, cC.x); fma2(acc[2][5], e2, cC.y);
                fma2(acc[2][6], e2, cD.x); fma2(acc[2][7], e2, cD.y);
                fma2(acc[3][0], e3, cA.x); fma2(acc[3][1], e3, cA.y);
                fma2(acc[3][2], e3, cB.x); fma2(acc[3][3], e3, cB.y);
                fma2(acc[3][4], e3, cC.x); fma2(acc[3][5], e3, cC.y);
                fma2(acc[3][6], e3, cD.x); fma2(acc[3][7], e3, cD.y);
                if (kx < LK_ - 1) {
                    cA = nA; cB = nB; cC = nC; cD = nD;
                    e0 = f0; e1 = f1; e2 = f2; e3 = f3;
                }
            }
        }
    }

    // ---- epilogue: fused dynamic 3x3 depthwise + store ----
#pragma unroll
    for (int p = 0; p < 4; p++) {
        int ly = ty4 + p;
        int gy = y0 + ly;
#pragma unroll
        for (int q = 0; q < 8; q++) {
            float2 v = unpk(acc[p][q]);
            float rr[2] = {v.x, v.y};
#pragma unroll
            for (int s = 0; s < 2; s++) {
                int c = coB + 2 * q + s;
                const float* ib = sIn + c * (ITH * ITW) + (ly + PADK - 1) * ITW + (tx + PADK - 1);
                const float* kk = sDk + c * 9;
                float dv = ib[0]          * kk[0] + ib[1]           * kk[1] + ib[2]           * kk[2]
                         + ib[ITW]        * kk[3] + ib[ITW + 1]     * kk[4] + ib[ITW + 2]     * kk[5]
                         + ib[2 * ITW]    * kk[6] + ib[2 * ITW + 1] * kk[7] + ib[2 * ITW + 2] * kk[8];
                out[(((size_t)b * C_ + c) * H_ + gy) * W_ + x0 + tx] = rr[s] + dv;
            }
        }
    }

    // ---- fused x2 passthrough copy for this tile (channels 32..63) ----
    for (int idx = tid; idx < PD * TYR * (TX / 4); idx += 256) {   // 4096 float4
        int ch2 = idx >> 7;
        int rem = idx & 127;
        int row = rem >> 2, c4 = rem & 3;
        size_t off = (((size_t)b * C_ + PD + ch2) * H_ + y0 + row) * W_ + x0 + c4 * 4;
        *(float4*)(out + off) = *(const float4*)(x + off);
    }
}

// ---------------- launch ----------------
extern "C" void kernel_launch(void* const* d_in, const int* in_sizes, int n_in,
                              void* d_out, int out_size) {
    const float* x  = (const float*)d_in[0];
    const float* lk = (const float*)d_in[1];
    const float* w1 = (const float*)d_in[2];
    const float* b1 = (const float*)d_in[3];
    const float* w2 = (const float*)d_in[4];
    const float* b2 = (const float*)d_in[5];
    float* out = (float*)d_out;

    const int smem_bytes = (IN_ELEMS + 2 * FSLICE + PD * 9) * (int)sizeof(float); // 207520
    cudaFuncSetAttribute(conv_main, cudaFuncAttributeMaxDynamicSharedMemorySize, smem_bytes);

    gap_kernel<<<B_ * PD, 256>>>(x);
    mlp_kernel<<<1, 288>>>(w1, b1, w2, b2);
    nop_kernel<<<1, 1>>>();   // aligns ncu's profiled launch index onto conv_main

    dim3 grid(W_ / TX, H_ / TYR, B_);
    conv_main<<<grid, 256, smem_bytes>>>(x, lk, out);
}

// round 8
// speedup vs baseline: 1.2690x; 1.0011x over previous
#include <cuda_runtime.h>
#include <cuda_bf16.h>
#include <math.h>

// Problem constants
#define B_   16
#define C_   64
#define H_   160
#define W_   160
#define PD   32
#define HW   (H_*W_)
#define LK_  13
#define PADK 6
#define TX   16          // tile width
#define TYR  32          // tile height
#define ITH  (TYR + 2*PADK)  // 44
#define ITW  (TX  + 2*PADK)  // 28
#define FSTRIDE 36           // filter [tap][co] stride (16B aligned at co 0/16)
#define FSLICE  (169*FSTRIDE)  // 6084 floats per ci slice
#define IN_ELEMS (PD*ITH*ITW)  // 39424

typedef unsigned long long ull;

__device__ float g_gap[B_ * PD];
__device__ float g_dk[B_ * PD * 9];

// ---------------- packed f32x2 helpers ----------------
__device__ __forceinline__ ull dup2(float a) {
    ull r;
    asm("mov.b64 %0, {%1, %1};" : "=l"(r) : "f"(a));
    return r;
}
__device__ __forceinline__ void fma2(ull& d, ull a, ull b) {
    asm("fma.rn.f32x2 %0, %1, %2, %0;" : "+l"(d) : "l"(a), "l"(b));
}
__device__ __forceinline__ float2 unpk(ull v) {
    float2 f;
    asm("mov.b64 {%0, %1}, %2;" : "=f"(f.x), "=f"(f.y) : "l"(v));
    return f;
}
__device__ __forceinline__ void cp4(float* dst, const float* src) {
    unsigned d = (unsigned)__cvta_generic_to_shared(dst);
    asm volatile("cp.async.ca.shared.global [%0], [%1], 4;" :: "r"(d), "l"(src));
}

// ---------------- kernel 1: GAP over H,W for first 32 ch ----------------
__global__ void gap_kernel(const float* __restrict__ x) {
    int bc = blockIdx.x;
    int b  = bc >> 5;
    int c  = bc & 31;
    const float4* p = (const float4*)(x + (size_t)(b * C_ + c) * HW);
    float s = 0.f;
    for (int i = threadIdx.x; i < HW / 4; i += 256) {
        float4 v = p[i];
        s += (v.x + v.y) + (v.z + v.w);
    }
    __shared__ float red[256];
    red[threadIdx.x] = s;
    __syncthreads();
    for (int st = 128; st > 0; st >>= 1) {
        if (threadIdx.x < st) red[threadIdx.x] += red[threadIdx.x + st];
        __syncthreads();
    }
    if (threadIdx.x == 0) g_gap[bc] = red[0] * (1.0f / (float)HW);
}

// ---------------- kernel 2: tiny MLP -> dk[b][c][3][3] ----------------
__global__ void mlp_kernel(const float* __restrict__ w1, const float* __restrict__ b1,
                           const float* __restrict__ w2, const float* __restrict__ b2) {
    __shared__ float h[B_ * 16];
    int t = threadIdx.x;           // 288 threads
    if (t < 256) {
        int b = t >> 4, j = t & 15;
        float s = b1[j];
#pragma unroll
        for (int c = 0; c < 32; c++) s += g_gap[b * 32 + c] * w1[j * 32 + c];
        h[t] = 0.5f * s * (1.0f + erff(s * 0.7071067811865476f));
    }
    __syncthreads();
    for (int idx = t; idx < B_ * 288; idx += 288) {
        int b = idx / 288, k = idx % 288;
        float s = b2[k];
#pragma unroll
        for (int j = 0; j < 16; j++) s += h[b * 16 + j] * w2[k * 16 + j];
        g_dk[idx] = s;
    }
}

// ---------------- profiling-alignment no-op ----------------
__global__ void nop_kernel() {}

// ---------------- main: 13x13 conv (32->32) + fused dyn 3x3 dw + x2 copy ----------------
// block: 256 threads; tx = tid&15, ty = (tid>>4)&7, tz = tid>>7 (warp-uniform tz)
// each thread: 4 y-pixels x 16 co (32 f32x2 accumulators); software-pipelined taps.
// grid: (10, 5, 16)
__global__ __launch_bounds__(256, 1)
void conv_main(const float* __restrict__ x, const float* __restrict__ flt,
               float* __restrict__ out) {
    extern __shared__ float sm[];
    float* sIn  = sm;                         // 39424 floats
    float* sFlt = sm + IN_ELEMS;              // 2 * 6084 floats (double buffered)
    float* sDk  = sFlt + 2 * FSLICE;          // 288 floats

    const int b   = blockIdx.z;
    const int x0  = blockIdx.x * TX;
    const int y0  = blockIdx.y * TYR;
    const int tid = threadIdx.x;
    const int tx  = tid & 15;
    const int ty  = (tid >> 4) & 7;
    const int tz  = tid >> 7;
    const int coB = tz * 16;
    const int ty4 = ty * 4;

    // ---- load input tile (32 ci, halo 6, zero padded) ----
    const float* xb = x + (size_t)b * C_ * HW;
    for (int i = tid; i < IN_ELEMS; i += 256) {
        int ci  = i / (ITH * ITW);
        int rem = i - ci * (ITH * ITW);
        int r = rem / ITW, c = rem - r * ITW;
        int gy = y0 - PADK + r, gx = x0 - PADK + c;
        float v = 0.f;
        if ((unsigned)gy < (unsigned)H_ && (unsigned)gx < (unsigned)W_)
            v = xb[ci * HW + gy * W_ + gx];
        sIn[i] = v;
    }
    for (int i = tid; i < PD * 9; i += 256) sDk[i] = g_dk[b * PD * 9 + i];

    // ---- stage filter slice ci=0 via cp.async (transposed to [tap][co]) ----
    {
        int co = tid >> 3, t0 = tid & 7;
        const float* src = flt + ((size_t)co * PD + 0) * 169;
        for (int t = t0; t < 169; t += 8) cp4(sFlt + t * FSTRIDE + co, src + t);
        asm volatile("cp.async.commit_group;" ::: "memory");
    }

    ull acc[4][8];
#pragma unroll
    for (int p = 0; p < 4; p++)
#pragma unroll
        for (int q = 0; q < 8; q++) acc[p][q] = 0ULL;

    for (int ci = 0; ci < PD; ci++) {
        asm volatile("cp.async.wait_group 0;" ::: "memory");
        __syncthreads();   // staged slice visible; prior compute done before overwrite
        if (ci + 1 < PD) {
            int co = tid >> 3, t0 = tid & 7;
            const float* src = flt + ((size_t)co * PD + ci + 1) * 169;
            float* dst = sFlt + ((ci + 1) & 1) * FSLICE;
            for (int t = t0; t < 169; t += 8) cp4(dst + t * FSTRIDE + co, src + t);
            asm volatile("cp.async.commit_group;" ::: "memory");
        }

        const float* fb  = sFlt + (ci & 1) * FSLICE;
        const float* inC = sIn + ci * (ITH * ITW);
#pragma unroll 1
        for (int ky = 0; ky < LK_; ky++) {
            const float* rbase = inC + (ty4 + ky) * ITW + tx;
            const float* wrow  = fb + (ky * LK_) * FSTRIDE + coB;

            // preload tap kx=0 (weights + inputs)
            ulonglong2 cA = *(const ulonglong2*)(wrow);
            ulonglong2 cB = *(const ulonglong2*)(wrow + 4);
            ulonglong2 cC = *(const ulonglong2*)(wrow + 8);
            ulonglong2 cD = *(const ulonglong2*)(wrow + 12);
            ull e0 = dup2(rbase[0]);
            ull e1 = dup2(rbase[ITW]);
            ull e2 = dup2(rbase[2 * ITW]);
            ull e3 = dup2(rbase[3 * ITW]);

#pragma unroll
            for (int kx = 0; kx < LK_; kx++) {
                ulonglong2 nA, nB, nC, nD;
                ull f0, f1, f2, f3;
                if (kx < LK_ - 1) {   // prefetch tap kx+1 before current FMAs
                    const float* wp = wrow + (kx + 1) * FSTRIDE;
                    nA = *(const ulonglong2*)(wp);
                    nB = *(const ulonglong2*)(wp + 4);
                    nC = *(const ulonglong2*)(wp + 8);
                    nD = *(const ulonglong2*)(wp + 12);
                    f0 = dup2(rbase[kx + 1]);
                    f1 = dup2(rbase[kx + 1 + ITW]);
                    f2 = dup2(rbase[kx + 1 + 2 * ITW]);
                    f3 = dup2(rbase[kx + 1 + 3 * ITW]);
                }
                fma2(acc[0][0], e0, cA.x); fma2(acc[0][1], e0, cA.y);
                fma2(acc[0][2], e0, cB.x); fma2(acc[0][3], e0, cB.y);
                fma2(acc[0][4], e0, cC.x); fma2(acc[0][5], e0, cC.y);
                fma2(acc[0][6], e0, cD.x); fma2(acc[0][7], e0, cD.y);
                fma2(acc[1][0], e1, cA.x); fma2(acc[1][1], e1, cA.y);
                fma2(acc[1][2], e1, cB.x); fma2(acc[1][3], e1, cB.y);
                fma2(acc[1][4], e1, cC.x); fma2(acc[1][5], e1, cC.y);
                fma2(acc[1][6], e1, cD.x); fma2(acc[1][7], e1, cD.y);
                fma2(acc[2][0], e2, cA.x); fma2(acc[2][1], e2, cA.y);
                fma2(acc[2][2], e2, cB.x); fma2(acc[2][3], e2, cB.y);
                fma2(acc[2][4], e2, cC.x); fma2(acc[2][5], e2, cC.y);
                fma2(acc[2][6], e2, cD.x); fma2(acc[2][7], e2, cD.y);
                fma2(acc[3][0], e3, cA.x); fma2(acc[3][1], e3, cA.y);
                fma2(acc[3][2], e3, cB.x); fma2(acc[3][3], e3, cB.y);
                fma2(acc[3][4], e3, cC.x); fma2(acc[3][5], e3, cC.y);
                fma2(acc[3][6], e3, cD.x); fma2(acc[3][7], e3, cD.y);
                if (kx < LK_ - 1) {
                    cA = nA; cB = nB; cC = nC; cD = nD;
                    e0 = f0; e1 = f1; e2 = f2; e3 = f3;
                }
            }
        }
    }

    // ---- epilogue: fused dynamic 3x3 depthwise + store ----
#pragma unroll
    for (int p = 0; p < 4; p++) {
        int ly = ty4 + p;
        int gy = y0 + ly;
#pragma unroll
        for (int q = 0; q < 8; q++) {
            float2 v = unpk(acc[p][q]);
            float rr[2] = {v.x, v.y};
#pragma unroll
            for (int s = 0; s < 2; s++) {
                int c = coB + 2 * q + s;
                const float* ib = sIn + c * (ITH * ITW) + (ly + PADK - 1) * ITW + (tx + PADK - 1);
                const float* kk = sDk + c * 9;
                float dv = ib[0]          * kk[0] + ib[1]           * kk[1] + ib[2]           * kk[2]
                         + ib[ITW]        * kk[3] + ib[ITW + 1]     * kk[4] + ib[ITW + 2]     * kk[5]
                         + ib[2 * ITW]    * kk[6] + ib[2 * ITW + 1] * kk[7] + ib[2 * ITW + 2] * kk[8];
                out[(((size_t)b * C_ + c) * H_ + gy) * W_ + x0 + tx] = rr[s] + dv;
            }
        }
    }

    // ---- fused x2 passthrough copy for this tile (channels 32..63) ----
    for (int idx = tid; idx < PD * TYR * (TX / 4); idx += 256) {   // 4096 float4
        int ch2 = idx >> 7;
        int rem = idx & 127;
        int row = rem >> 2, c4 = rem & 3;
        size_t off = (((size_t)b * C_ + PD + ch2) * H_ + y0 + row) * W_ + x0 + c4 * 4;
        *(float4*)(out + off) = *(const float4*)(x + off);
    }
}

// ---------------- launch ----------------
extern "C" void kernel_launch(void* const* d_in, const int* in_sizes, int n_in,
                              void* d_out, int out_size) {
    const float* x  = (const float*)d_in[0];
    const float* lk = (const float*)d_in[1];
    const float* w1 = (const float*)d_in[2];
    const float* b1 = (const float*)d_in[3];
    const float* w2 = (const float*)d_in[4];
    const float* b2 = (const float*)d_in[5];
    float* out = (float*)d_out;

    const int smem_bytes = (IN_ELEMS + 2 * FSLICE + PD * 9) * (int)sizeof(float); // 207520
    cudaFuncSetAttribute(conv_main, cudaFuncAttributeMaxDynamicSharedMemorySize, smem_bytes);

    gap_kernel<<<B_ * PD, 256>>>(x);
    mlp_kernel<<<1, 288>>>(w1, b1, w2, b2);
    nop_kernel<<<1, 1>>>();   // aligns ncu's profiled launch index onto conv_main

    dim3 grid(W_ / TX, H_ / TYR, B_);
    conv_main<<<grid, 256, smem_bytes>>>(x, lk, out);
}

// round 10
// speedup vs baseline: 3.0536x; 2.4063x over previous
#include <cuda_runtime.h>
#include <cuda_bf16.h>
#include <math.h>
#include <stdint.h>

#define B_ 16
#define C_ 64
#define HH 160
#define WW 160
#define PD 32
#define HW (HH*WW)
#define NTAP 169

// conv tile geometry
#define TOX 32
#define TOY 16
#define PW  44              // padded tile width  (TOX+12)
#define PH  28              // padded tile height (TOY+12)
#define NIN (PW*PH)         // 1232 input pixels resident
#define THR 256

__device__ float g_gap[B_*PD];
__device__ float g_dk[B_*PD*9];
__device__ __align__(16) unsigned char g_xhl[(size_t)B_*HW*128];       // [b][pix][hi64B|lo64B]
__device__ __align__(16) unsigned char g_wb[(size_t)B_*NTAP*PD*128];   // [b][tap][co][hi|lo]

// ---------------- helpers ----------------
__device__ __forceinline__ uint32_t smem_u32(const void* p){
    uint32_t a; asm("{ .reg .u64 t; cvta.to.shared.u64 t, %1; cvt.u32.u64 %0, t; }":"=r"(a):"l"(p)); return a;
}
__device__ __forceinline__ void cp16(uint32_t dst, const void* src){
    asm volatile("cp.async.ca.shared.global [%0], [%1], 16;"::"r"(dst),"l"(src));
}
__device__ __forceinline__ void cp16z(uint32_t dst, const void* src, bool ok, const void* safe){
    int sz = ok?16:0; const void* s = ok?src:safe;
    asm volatile("cp.async.ca.shared.global [%0], [%1], 16, %2;"::"r"(dst),"l"(s),"r"(sz));
}
#define CPCOMMIT() asm volatile("cp.async.commit_group;":::"memory")
#define CPWAIT6()  asm volatile("cp.async.wait_group 6;":::"memory")

#define LDSM_X4(r, a) asm volatile("ldmatrix.sync.aligned.m8n8.x4.shared.b16 {%0,%1,%2,%3}, [%4];" \
    : "=r"((r)[0]),"=r"((r)[1]),"=r"((r)[2]),"=r"((r)[3]) : "r"(a))
#define LDSM_X2(r, a) asm volatile("ldmatrix.sync.aligned.m8n8.x2.shared.b16 {%0,%1}, [%2];" \
    : "=r"((r)[0]),"=r"((r)[1]) : "r"(a))
#define MMA16816(d, a, b2) asm volatile( \
    "mma.sync.aligned.m16n8k16.row.col.f32.bf16.bf16.f32 {%0,%1,%2,%3}, {%4,%5,%6,%7}, {%8,%9}, {%0,%1,%2,%3};" \
    : "+f"((d)[0]), "+f"((d)[1]), "+f"((d)[2]), "+f"((d)[3]) \
    : "r"((a)[0]), "r"((a)[1]), "r"((a)[2]), "r"((a)[3]), "r"((b2)[0]), "r"((b2)[1]))

// ---------------- kernel 1: GAP ----------------
__global__ void gap_kernel(const float* __restrict__ x){
    int bc = blockIdx.x, b = bc>>5, c = bc&31;
    const float4* p = (const float4*)(x + (size_t)(b*C_+c)*HW);
    float s = 0.f;
    for (int i = threadIdx.x; i < HW/4; i += 256){ float4 v = p[i]; s += (v.x+v.y)+(v.z+v.w); }
    __shared__ float red[256];
    red[threadIdx.x] = s; __syncthreads();
    for (int st=128; st>0; st>>=1){ if (threadIdx.x<st) red[threadIdx.x]+=red[threadIdx.x+st]; __syncthreads(); }
    if (threadIdx.x==0) g_gap[bc] = red[0]*(1.0f/(float)HW);
}

// ---------------- kernel 2: MLP -> dk ----------------
__global__ void mlp_kernel(const float* __restrict__ w1, const float* __restrict__ b1,
                           const float* __restrict__ w2, const float* __restrict__ b2){
    __shared__ float h[B_*16];
    int t = threadIdx.x;
    if (t < 256){
        int b = t>>4, j = t&15; float s = b1[j];
#pragma unroll
        for (int c=0;c<32;c++) s += g_gap[b*32+c]*w1[j*32+c];
        h[t] = 0.5f*s*(1.0f+erff(s*0.7071067811865476f));
    }
    __syncthreads();
    for (int idx=t; idx<B_*288; idx+=288){
        int b = idx/288, k = idx%288; float s = b2[k];
#pragma unroll
        for (int j=0;j<16;j++) s += h[b*16+j]*w2[k*16+j];
        g_dk[idx] = s;
    }
}

// ---------------- kernel 3: pack x1 -> pixel-major hi/lo bf16 ----------------
__global__ void prep_x(const float* __restrict__ x){
    __shared__ float s[32*256];
    int b = blockIdx.y, px0 = blockIdx.x*256, t = threadIdx.x;
    const float* xb = x + (size_t)b*C_*HW + px0;
#pragma unroll
    for (int ci=0; ci<32; ci++) s[ci*256+t] = xb[(size_t)ci*HW + t];
    __syncthreads();
    uint32_t hi[16], lo[16];
#pragma unroll
    for (int k=0;k<16;k++){
        float v0 = s[(2*k)*256+t],  v1 = s[(2*k+1)*256+t];
        __nv_bfloat16 h0 = __float2bfloat16(v0), h1 = __float2bfloat16(v1);
        __nv_bfloat16 l0 = __float2bfloat16(v0-__bfloat162float(h0));
        __nv_bfloat16 l1 = __float2bfloat16(v1-__bfloat162float(h1));
        hi[k] = (uint32_t)__bfloat16_as_ushort(h0) | ((uint32_t)__bfloat16_as_ushort(h1)<<16);
        lo[k] = (uint32_t)__bfloat16_as_ushort(l0) | ((uint32_t)__bfloat16_as_ushort(l1)<<16);
    }
    uint4* dst = (uint4*)(g_xhl + ((size_t)(b*HW + px0 + t)<<7));
#pragma unroll
    for (int k=0;k<4;k++) dst[k]   = make_uint4(hi[4*k],hi[4*k+1],hi[4*k+2],hi[4*k+3]);
#pragma unroll
    for (int k=0;k<4;k++) dst[4+k] = make_uint4(lo[4*k],lo[4*k+1],lo[4*k+2],lo[4*k+3]);
}

// ---------------- kernel 4: weights + folded dyn-3x3 -> per-batch bf16 hi/lo blob ----------------
__global__ void prep_w(const float* __restrict__ flt){
    __shared__ float ws[1024];
    int tap = blockIdx.x, t = threadIdx.x;
    for (int i=t; i<1024; i+=256) ws[i] = flt[(size_t)i*NTAP + tap];  // ws[co*32+ci]
    __syncthreads();
    int ky = tap/13, kx = tap-13*ky;
    bool center = (ky>=5 && ky<=7 && kx>=5 && kx<=7);
    int dkt = (ky-5)*3 + (kx-5);
    for (int task=t; task<512; task+=256){
        int b = task>>5, co = task&31;
        uint32_t hi[16], lo[16];
#pragma unroll
        for (int k=0;k<16;k++){
            float v0 = ws[co*32+2*k], v1 = ws[co*32+2*k+1];
            if (center && (2*k)==co)   v0 += g_dk[b*288+co*9+dkt];
            if (center && (2*k+1)==co) v1 += g_dk[b*288+co*9+dkt];
            __nv_bfloat16 h0 = __float2bfloat16(v0), h1 = __float2bfloat16(v1);
            __nv_bfloat16 l0 = __float2bfloat16(v0-__bfloat162float(h0));
            __nv_bfloat16 l1 = __float2bfloat16(v1-__bfloat162float(h1));
            hi[k] = (uint32_t)__bfloat16_as_ushort(h0) | ((uint32_t)__bfloat16_as_ushort(h1)<<16);
            lo[k] = (uint32_t)__bfloat16_as_ushort(l0) | ((uint32_t)__bfloat16_as_ushort(l1)<<16);
        }
        uint4* dst = (uint4*)(g_wb + ((size_t)((b*NTAP+tap)*PD + co)<<7));
#pragma unroll
        for (int k=0;k<4;k++) dst[k]   = make_uint4(hi[4*k],hi[4*k+1],hi[4*k+2],hi[4*k+3]);
#pragma unroll
        for (int k=0;k<4;k++) dst[4+k] = make_uint4(lo[4*k],lo[4*k+1],lo[4*k+2],lo[4*k+3]);
    }
}

// ---------------- profiling-alignment no-op ----------------
__global__ void nop_kernel() {}

// ---------------- main: mma.sync implicit 13x13 conv + x2 copy ----------------
// 256 thr = 8 warps. Per warp: 64 out px (4 m16 tiles) x 32 co. 3-term bf16 split.
// grid (5, 10, 16). B ring: 8 slots x 4KB, cp.async distance-6 groups.
__global__ __launch_bounds__(THR, 1)
void conv_mma(const float* __restrict__ x, float* __restrict__ out){
    extern __shared__ unsigned char smraw[];
    uint32_t sb    = smem_u32(smraw);
    uint32_t ain   = (sb + 127) & ~127u;
    uint32_t bbase = ain + NIN*128;

    const int b  = blockIdx.z;
    const int X0 = blockIdx.x*TOX;
    const int Y0 = blockIdx.y*TOY;
    const int tid = threadIdx.x;
    const int w = tid>>5, l = tid&31;
    const unsigned char* wbb = g_wb + ((size_t)b*NTAP*PD<<7);

    // ---- stage input tile (swizzled, zero halo) : cp.async group 0 ----
    for (int i=tid; i<NIN*8; i+=THR){
        int px = i>>3, j = i&7;
        int ly = px/PW, lx = px - ly*PW;
        int gy = Y0-6+ly, gx = X0-6+lx;
        bool ok = ((unsigned)gy<(unsigned)HH) & ((unsigned)gx<(unsigned)WW);
        uint32_t off = ((uint32_t)px<<7) + ((uint32_t)j<<4);
        cp16z(ain + (off ^ ((off>>3)&0x70)), g_xhl + (((size_t)(b*HW + gy*WW + gx))<<7) + (j<<4), ok, g_xhl);
    }
    // ---- stage B slices 0..5 : groups 0..5 ----
#pragma unroll
    for (int s=0; s<6; s++){
        uint32_t off = (uint32_t)tid<<4;
        cp16(bbase + ((uint32_t)s<<12) + (off ^ ((off>>3)&0x70)), wbb + (((size_t)s)<<12) + off);
        CPCOMMIT();
    }

    // ---- per-lane constants ----
    const int r = (l&7) + ((l>>3)&1)*8;          // A matrix row -> x offset
    const uint32_t akb = ((uint32_t)(l>>4)&1)*16; // A k-half byte select
    uint32_t pb[4];
#pragma unroll
    for (int i=0;i<4;i++) pb[i] = (uint32_t)((2*w + (i>>1))*PW + (i&1)*16 + r);
    const uint32_t bph   = ((uint32_t)(l&7))<<4;      // B swizzle phase (co&7)
    const uint32_t brow  = ((uint32_t)(l>>3)&1)*16;   // B matrix1 k-offset
    const uint32_t boffL = ((uint32_t)(l&7))<<7;      // B co row within group

    float d[4][4][4];
#pragma unroll
    for (int i=0;i<4;i++)
#pragma unroll
        for (int g=0;g<4;g++){ d[i][g][0]=0.f; d[i][g][1]=0.f; d[i][g][2]=0.f; d[i][g][3]=0.f; }

    int dp = 0, kx = 0;
    for (int t=0; t<NTAP; t++){
        int nt = t+6;
        if (nt < NTAP){
            uint32_t off = (uint32_t)tid<<4;
            cp16(bbase + ((uint32_t)(nt&7)<<12) + (off ^ ((off>>3)&0x70)), wbb + (((size_t)nt)<<12) + off);
        }
        CPCOMMIT();
        CPWAIT6();              // tap t's B (and input at t=0) landed
        __syncthreads();

        uint32_t bslot = bbase + ((uint32_t)(t&7)<<12);
        uint32_t bh[4][2][2], bl[4][2][2];
#pragma unroll
        for (int g=0; g<4; g++){
            uint32_t bg = bslot + ((uint32_t)g<<10) + boffL;
            LDSM_X2(bh[g][0], bg + ((  0 + brow) ^ bph));
            LDSM_X2(bh[g][1], bg + (( 32 + brow) ^ bph));
            LDSM_X2(bl[g][0], bg + (( 64 + brow) ^ bph));
            LDSM_X2(bl[g][1], bg + (( 96 + brow) ^ bph));
        }
#pragma unroll
        for (int i=0; i<4; i++){
            uint32_t p    = pb[i] + (uint32_t)dp;
            uint32_t base = ain + (p<<7);
            uint32_t ph   = (p&7)<<4;
            uint32_t ah0[4], ah1[4], al0[4], al1[4];
            LDSM_X4(ah0, base + ((akb +  0) ^ ph));
            LDSM_X4(ah1, base + ((akb + 32) ^ ph));
            LDSM_X4(al0, base + ((akb + 64) ^ ph));
            LDSM_X4(al1, base + ((akb + 96) ^ ph));
#pragma unroll
            for (int g=0; g<4; g++){
                MMA16816(d[i][g], ah0, bh[g][0]);
                MMA16816(d[i][g], ah1, bh[g][1]);
                MMA16816(d[i][g], ah0, bl[g][0]);
                MMA16816(d[i][g], ah1, bl[g][1]);
                MMA16816(d[i][g], al0, bh[g][0]);
                MMA16816(d[i][g], al1, bh[g][1]);
            }
        }
        if (++kx == 13){ kx = 0; dp += PW - 12; } else { dp++; }
    }

    // ---- epilogue: store D ----
#pragma unroll
    for (int i=0; i<4; i++){
        int y   = Y0 + 2*w + (i>>1);
        int xb2 = X0 + (i&1)*16;
        int r0  = l>>2;
#pragma unroll
        for (int g=0; g<4; g++){
            int co = g*8 + (l&3)*2;
            float* o0 = out + (((size_t)b*C_ + co)*HH + y)*WW + xb2;
            float* o1 = o0 + HW;
            o0[r0]     = d[i][g][0];
            o1[r0]     = d[i][g][1];
            o0[r0 + 8] = d[i][g][2];
            o1[r0 + 8] = d[i][g][3];
        }
    }

    // ---- fused x2 passthrough copy (channels 32..63, this tile) ----
    for (int i=tid; i<PD*TOY*TOX/4; i+=THR){   // 4096 float4
        int ch = i>>7;
        int rem = i&127;
        int row = rem>>3, c4 = rem&7;
        size_t off = (((size_t)b*C_ + PD + ch)*HH + Y0+row)*WW + X0 + (c4<<2);
        *(float4*)(out+off) = *(const float4*)(x+off);
    }
}

// ---------------- launch ----------------
extern "C" void kernel_launch(void* const* d_in, const int* in_sizes, int n_in,
                              void* d_out, int out_size){
    const float* x  = (const float*)d_in[0];
    const float* lk = (const float*)d_in[1];
    const float* w1 = (const float*)d_in[2];
    const float* b1 = (const float*)d_in[3];
    const float* w2 = (const float*)d_in[4];
    const float* b2 = (const float*)d_in[5];
    float* out = (float*)d_out;

    const int smem_bytes = 128 + NIN*128 + 8*4096;   // 190592
    cudaFuncSetAttribute(conv_mma, cudaFuncAttributeMaxDynamicSharedMemorySize, smem_bytes);

    gap_kernel<<<B_*PD, 256>>>(x);
    mlp_kernel<<<1, 288>>>(w1, b1, w2, b2);
    prep_x<<<dim3(HW/256, B_), 256>>>(x);
    prep_w<<<NTAP, 256>>>(lk);
    nop_kernel<<<1, 1>>>();   // 6 launches/iter -> ncu (-s 5 -c 1) lands on conv_mma

    conv_mma<<<dim3(WW/TOX, HH/TOY, B_), THR, smem_bytes>>>(x, out);
}